// round 10
// baseline (speedup 1.0000x reference)
#include <cuda_runtime.h>

// Problem constants (fixed by the reference setup_inputs)
#define BB 8
#define CC 512
#define RR 128
#define HW (128 * 128)
#define NPLANE (BB * CC)
#define QV (HW / 4 / 4)           // float4 elements per QUARTER plane (1024)
#define NQ (4 * CC)               // quarter-plane CTAs per batch (2048)

// Scratch (no allocations allowed in kernel_launch)
__device__ float g_part[NPLANE * 4];      // quarter-plane partial sums
__device__ float g_y1[BB * RR];           // relu6(w_guide @ mean) per batch

// ---------------------------------------------------------------------------
// Inline bias (warp 0): bias = relu6(BN(dot(w_fuse[c,:], y1[b]))).
// ---------------------------------------------------------------------------
__device__ __forceinline__ float get_bias(
    const float* __restrict__ w_fuse,
    const float* __restrict__ bn_gamma, const float* __restrict__ bn_beta,
    const float* __restrict__ bn_mean,  const float* __restrict__ bn_var,
    int b, int c, int tid) {
    __shared__ float bsh;
    const int lane = tid & 31;
    if (tid < 32) {
        const float4* __restrict__ row =
            reinterpret_cast<const float4*>(w_fuse + (size_t)c * RR);
        const float4* __restrict__ y14 =
            reinterpret_cast<const float4*>(g_y1 + b * RR);
        float4 w = row[lane];
        float4 y = y14[lane];
        float acc = w.x * y.x;
        acc = fmaf(w.y, y.y, acc);
        acc = fmaf(w.z, y.z, acc);
        acc = fmaf(w.w, y.w, acc);
#pragma unroll
        for (int o = 16; o > 0; o >>= 1)
            acc += __shfl_xor_sync(0xffffffffu, acc, o);
        if (lane == 0) {
            const float inv_std = rsqrtf(bn_var[c] + 1e-5f);
            float v = fmaf((acc - bn_mean[c]) * inv_std, bn_gamma[c], bn_beta[c]);
            bsh = fminf(fmaxf(v, 0.0f), 6.0f);
        }
    }
    __syncthreads();
    return bsh;
}

// CTA-level sum finisher: warp reduce + cross-warp, writes g_part slot.
__device__ __forceinline__ void finish_sum(float s, int slot, int tid) {
#pragma unroll
    for (int o = 16; o > 0; o >>= 1)
        s += __shfl_xor_sync(0xffffffffu, s, o);
    __shared__ float ws[8];
    if ((tid & 31) == 0) ws[tid >> 5] = s;
    __syncthreads();
    if (tid < 8) {
        float t = ws[tid];
#pragma unroll
        for (int o = 4; o > 0; o >>= 1)
            t += __shfl_xor_sync(0x000000ffu, t, o);
        if (tid == 0) g_part[slot] = t;
    }
}

// ---------------------------------------------------------------------------
// Mid body: y1[b][r] = relu6((w_guide[r,:] @ sums[b]) / HW), one warp per r.
// sums[b][c] = hsum(g_part4[b*CC + c])  (4 quarter partials = one float4).
// ---------------------------------------------------------------------------
__device__ __forceinline__ void mid_body(const float* __restrict__ w_guide,
                                         int b, int r, int lane) {
    const float4* __restrict__ row =
        reinterpret_cast<const float4*>(w_guide + (size_t)r * CC);
    const float4* __restrict__ pp =
        reinterpret_cast<const float4*>(g_part + (size_t)b * CC * 4);

    float acc = 0.0f;
#pragma unroll
    for (int j = 0; j < 4; ++j) {
        float4 w = row[lane + 32 * j];
        const int c0 = 4 * (lane + 32 * j);
        float4 a0 = pp[c0], a1 = pp[c0 + 1], a2 = pp[c0 + 2], a3 = pp[c0 + 3];
        acc = fmaf(w.x, (a0.x + a0.y) + (a0.z + a0.w), acc);
        acc = fmaf(w.y, (a1.x + a1.y) + (a1.z + a1.w), acc);
        acc = fmaf(w.z, (a2.x + a2.y) + (a2.z + a2.w), acc);
        acc = fmaf(w.w, (a3.x + a3.y) + (a3.z + a3.w), acc);
    }
#pragma unroll
    for (int o = 16; o > 0; o >>= 1)
        acc += __shfl_xor_sync(0xffffffffu, acc, o);
    if (lane == 0) {
        float v = acc * (1.0f / (float)HW);
        g_y1[b * RR + r] = fminf(fmaxf(v, 0.0f), 6.0f);
    }
}

// ---------------------------------------------------------------------------
// Unified phase kernel. bid < NQ: streaming CTA handling quarter q of plane c
// (c = bid>>2, q = bid&3) — role depends on which of addB/redB are valid:
//   both  : fused  (add old batch quarter + reduce new batch quarter)
//   addB  : add only        redB : reduce only
// bid >= NQ: mid CTAs for batch midB (16 CTAs x 8 warps).
// All dependencies cross launch boundaries — no sync instructions.
// ---------------------------------------------------------------------------
__global__ __launch_bounds__(256) void phase_kernel(
    const float* __restrict__ x, float* __restrict__ out,
    const float* __restrict__ w_guide,
    const float* __restrict__ w_fuse,
    const float* __restrict__ bn_gamma, const float* __restrict__ bn_beta,
    const float* __restrict__ bn_mean,  const float* __restrict__ bn_var,
    int addB, int midB, int redB) {
    const int bid = blockIdx.x;
    const int tid = threadIdx.x;

    if (bid >= NQ) {                       // mid CTAs
        const int r = (bid - NQ) * 8 + (tid >> 5);
        mid_body(w_guide, midB, r, tid & 31);
        return;
    }

    const int c = bid >> 2;
    const int q = bid & 3;

    const bool hasAdd = (addB >= 0);
    const bool hasRed = (redB < BB);

    float bias = 0.0f;
    if (hasAdd)
        bias = get_bias(w_fuse, bn_gamma, bn_beta, bn_mean, bn_var, addB, c, tid);

    const float4* __restrict__ pOld = hasAdd
        ? reinterpret_cast<const float4*>(x + ((size_t)addB * CC + c) * HW) + q * QV
        : nullptr;
    float4* __restrict__ pOut = hasAdd
        ? reinterpret_cast<float4*>(out + ((size_t)addB * CC + c) * HW) + q * QV
        : nullptr;
    const float4* __restrict__ pNew = hasRed
        ? reinterpret_cast<const float4*>(x + ((size_t)redB * CC + c) * HW) + q * QV
        : nullptr;

    float s = 0.0f;
    if (hasAdd && hasRed) {
#pragma unroll
        for (int i = 0; i < QV / 256; ++i) {
            float4 a = __ldcs(&pOld[tid + i * 256]);      // L2-resident, dead after
            float4 n = pNew[tid + i * 256];               // DRAM, keep in L2
            a.x += bias; a.y += bias; a.z += bias; a.w += bias;
            __stcs(&pOut[tid + i * 256], a);
            s += (n.x + n.y) + (n.z + n.w);
        }
    } else if (hasAdd) {
#pragma unroll
        for (int i = 0; i < QV / 256; ++i) {
            float4 a = __ldcs(&pOld[tid + i * 256]);
            a.x += bias; a.y += bias; a.z += bias; a.w += bias;
            __stcs(&pOut[tid + i * 256], a);
        }
    } else {
#pragma unroll
        for (int i = 0; i < QV / 256; ++i) {
            float4 n = pNew[tid + i * 256];
            s += (n.x + n.y) + (n.z + n.w);
        }
    }

    if (hasRed)
        finish_sum(s, ((size_t)redB * CC + c) * 4 + q, tid);
}

extern "C" void kernel_launch(void* const* d_in, const int* in_sizes, int n_in,
                              void* d_out, int out_size) {
    const float* x        = (const float*)d_in[0];
    const float* w_guide  = (const float*)d_in[1];
    const float* w_fuse   = (const float*)d_in[2];
    const float* bn_gamma = (const float*)d_in[3];
    const float* bn_beta  = (const float*)d_in[4];
    const float* bn_mean  = (const float*)d_in[5];
    const float* bn_var   = (const float*)d_in[6];
    float* out = (float*)d_out;

    const int NMID = RR / 8;   // 16 CTAs, 8 warps each

    // Depth-2 pipeline: launch p does add(p-2) + mid(p-1) + red(p),
    // with add+red fused into uniform quarter-plane CTAs.
    for (int p = 0; p <= BB + 1; ++p) {
        const int addB = p - 2;                       // -1/-2 => no add
        const int midB = p - 1;
        const int redB = p;                           // >= BB => no red
        const bool hasMid = (midB >= 0 && midB < BB);
        const int grid = NQ + (hasMid ? NMID : 0);
        phase_kernel<<<grid, 256>>>(
            x, out, w_guide, w_fuse, bn_gamma, bn_beta, bn_mean, bn_var,
            (addB >= 0) ? addB : -1, hasMid ? midB : 0, redB);
    }
}

// round 11
// speedup vs baseline: 1.0903x; 1.0903x over previous
#include <cuda_runtime.h>

// Problem constants (fixed by the reference setup_inputs)
#define BB 8
#define CC 512
#define RR 128
#define HW (128 * 128)
#define NPLANE (BB * CC)
#define HV (HW / 4 / 2)           // float4 elements per HALF plane (2048)

// Scratch (no allocations allowed in kernel_launch)
__device__ float g_part[NPLANE * 2];      // half-plane partial sums
__device__ float g_y1[BB * RR];           // relu6(w_guide @ mean) per batch

// ---------------------------------------------------------------------------
// Half-plane reduce: one 256-thread CTA sums 8192 floats (8 float4/thread).
// Default-policy reads: keep the new batch resident in L2 for its later add.
// ---------------------------------------------------------------------------
__device__ __forceinline__ void half_reduce(const float* __restrict__ x,
                                            int plane, int half, int tid) {
    const float4* __restrict__ p =
        reinterpret_cast<const float4*>(x + (size_t)plane * HW) + half * HV;
    float s = 0.0f;
#pragma unroll
    for (int i = 0; i < HV / 256; ++i) {
        float4 v = p[tid + i * 256];
        s += (v.x + v.y) + (v.z + v.w);
    }
#pragma unroll
    for (int o = 16; o > 0; o >>= 1)
        s += __shfl_xor_sync(0xffffffffu, s, o);

    __shared__ float ws[8];
    if ((tid & 31) == 0) ws[tid >> 5] = s;
    __syncthreads();
    if (tid < 8) {
        float t = ws[tid];
#pragma unroll
        for (int o = 4; o > 0; o >>= 1)
            t += __shfl_xor_sync(0x000000ffu, t, o);
        if (tid == 0) g_part[plane * 2 + half] = t;
    }
}

// ---------------------------------------------------------------------------
// Half-plane add with inline bias: warp 0 computes
//   bias = relu6(BN(dot(w_fuse[c,:], y1[b])))
// then all warps stream out = x + bias. Evict-first reads (dead after) and
// stores (protect the L2-resident reduce stream).
// ---------------------------------------------------------------------------
__device__ __forceinline__ void half_add(
    const float* __restrict__ x, float* __restrict__ out,
    const float* __restrict__ w_fuse,
    const float* __restrict__ bn_gamma, const float* __restrict__ bn_beta,
    const float* __restrict__ bn_mean,  const float* __restrict__ bn_var,
    int b, int c, int half, int tid) {
    __shared__ float bsh;
    const int lane = tid & 31;

    if (tid < 32) {
        const float4* __restrict__ row =
            reinterpret_cast<const float4*>(w_fuse + (size_t)c * RR);
        const float4* __restrict__ y14 =
            reinterpret_cast<const float4*>(g_y1 + b * RR);
        float4 w = row[lane];
        float4 y = y14[lane];
        float acc = w.x * y.x;
        acc = fmaf(w.y, y.y, acc);
        acc = fmaf(w.z, y.z, acc);
        acc = fmaf(w.w, y.w, acc);
#pragma unroll
        for (int o = 16; o > 0; o >>= 1)
            acc += __shfl_xor_sync(0xffffffffu, acc, o);
        if (lane == 0) {
            const float inv_std = rsqrtf(bn_var[c] + 1e-5f);
            float v = fmaf((acc - bn_mean[c]) * inv_std, bn_gamma[c], bn_beta[c]);
            bsh = fminf(fmaxf(v, 0.0f), 6.0f);
        }
    }
    __syncthreads();
    const float bias = bsh;

    const int plane = b * CC + c;
    const float4* __restrict__ p =
        reinterpret_cast<const float4*>(x + (size_t)plane * HW) + half * HV;
    float4* __restrict__ o =
        reinterpret_cast<float4*>(out + (size_t)plane * HW) + half * HV;
#pragma unroll
    for (int i = 0; i < HV / 256; ++i) {
        float4 v = __ldcs(&p[tid + i * 256]);
        v.x += bias; v.y += bias; v.z += bias; v.w += bias;
        __stcs(&o[tid + i * 256], v);
    }
}

// ---------------------------------------------------------------------------
// Mid body: y1[b][r] = relu6((w_guide[r,:] @ sums[b]) / HW), one warp per r.
// sums[b][c] = g_part[(b*CC+c)*2] + g_part[(b*CC+c)*2+1].
// ---------------------------------------------------------------------------
__device__ __forceinline__ void mid_body(const float* __restrict__ w_guide,
                                         int b, int r, int lane) {
    const float4* __restrict__ row =
        reinterpret_cast<const float4*>(w_guide + (size_t)r * CC);
    const float4* __restrict__ pp =
        reinterpret_cast<const float4*>(g_part + (size_t)b * CC * 2);

    float acc = 0.0f;
#pragma unroll
    for (int j = 0; j < 4; ++j) {
        float4 w  = row[lane + 32 * j];
        float4 a0 = pp[2 * (lane + 32 * j)];
        float4 a1 = pp[2 * (lane + 32 * j) + 1];
        acc = fmaf(w.x, a0.x + a0.y, acc);
        acc = fmaf(w.y, a0.z + a0.w, acc);
        acc = fmaf(w.z, a1.x + a1.y, acc);
        acc = fmaf(w.w, a1.z + a1.w, acc);
    }
#pragma unroll
    for (int o = 16; o > 0; o >>= 1)
        acc += __shfl_xor_sync(0xffffffffu, acc, o);
    if (lane == 0) {
        float v = acc * (1.0f / (float)HW);
        g_y1[b * RR + r] = fminf(fmaxf(v, 0.0f), 6.0f);
    }
}

// ---------------------------------------------------------------------------
// Unified phase kernel, 2-batch granularity. CTA ranges (by blockIdx.x):
//   [0, nAdd)          : add  half-planes of batches addB0, addB0+1
//   [nAdd, nAdd+nMid)  : mid  batches midB0, midB0+1 (16 CTAs each)
//   [nAdd+nMid, ...)   : red  half-planes of batches redB0, redB0+1
// All dependencies cross launch boundaries — no sync instructions.
// ---------------------------------------------------------------------------
__global__ __launch_bounds__(256) void phase_kernel(
    const float* __restrict__ x, float* __restrict__ out,
    const float* __restrict__ w_guide,
    const float* __restrict__ w_fuse,
    const float* __restrict__ bn_gamma, const float* __restrict__ bn_beta,
    const float* __restrict__ bn_mean,  const float* __restrict__ bn_var,
    int addB0, int midB0, int redB0, int nAdd, int nMid) {
    const int bid = blockIdx.x;
    const int tid = threadIdx.x;

    if (bid < nAdd) {
        const int p = bid >> 1;                  // 0..1023 across 2 batches
        half_add(x, out, w_fuse, bn_gamma, bn_beta, bn_mean, bn_var,
                 addB0 + (p >> 9), p & (CC - 1), bid & 1, tid);
    } else if (bid < nAdd + nMid) {
        const int m = bid - nAdd;                // 0..31
        const int b = midB0 + (m >> 4);
        const int r = (m & 15) * 8 + (tid >> 5);
        mid_body(w_guide, b, r, tid & 31);
    } else {
        const int rid = bid - nAdd - nMid;
        const int p = rid >> 1;
        half_reduce(x, (redB0 + (p >> 9)) * CC + (p & (CC - 1)), rid & 1, tid);
    }
}

extern "C" void kernel_launch(void* const* d_in, const int* in_sizes, int n_in,
                              void* d_out, int out_size) {
    const float* x        = (const float*)d_in[0];
    const float* w_guide  = (const float*)d_in[1];
    const float* w_fuse   = (const float*)d_in[2];
    const float* bn_gamma = (const float*)d_in[3];
    const float* bn_beta  = (const float*)d_in[4];
    const float* bn_mean  = (const float*)d_in[5];
    const float* bn_var   = (const float*)d_in[6];
    float* out = (float*)d_out;

    // Depth-2 pipeline at 2-batch granularity, 6 launches:
    //   L_p: add(2p-4, 2p-3) + mid(2p-2, 2p-1) + red(2p, 2p+1)
    for (int p = 0; p < 6; ++p) {
        const int addB0 = 2 * p - 4;
        const int midB0 = 2 * p - 2;
        const int redB0 = 2 * p;
        const int nAdd = (addB0 >= 0) ? 4 * CC : 0;          // 2048
        const int nMid = (midB0 >= 0 && midB0 < BB) ? 32 : 0;
        const int nRed = (redB0 < BB) ? 4 * CC : 0;          // 2048
        phase_kernel<<<nAdd + nMid + nRed, 256>>>(
            x, out, w_guide, w_fuse, bn_gamma, bn_beta, bn_mean, bn_var,
            addB0, (nMid ? midB0 : 0), redB0, nAdd, nMid);
    }
}

// round 12
// speedup vs baseline: 1.1899x; 1.0914x over previous
#include <cuda_runtime.h>

// Problem constants (fixed by the reference setup_inputs)
#define BB 8
#define CC 512
#define RR 128
#define HW (128 * 128)
#define NPLANE (BB * CC)
#define HV (HW / 4 / 2)           // float4 elements per HALF plane (2048)

#define PAIRS 4                   // batch pairs (0,1) (2,3) (4,5) (6,7)
#define REDN 2048                 // red CTAs per pair (2 batches x 1024 half-planes)
#define MIDN 32                   // mid CTAs per pair (2 batches x 16)
#define ADDN 2048                 // add CTAs per pair
#define SEG (REDN + MIDN + ADDN)  // 4128

// Scratch (no allocations allowed in kernel_launch)
__device__ __align__(16) float g_part[NPLANE * 2];  // half-plane partial sums
__device__ __align__(16) float g_y1[BB * RR];       // relu6(w_guide @ mean)
__device__ int g_redCnt[PAIRS];   // reds done per pair       (self-resetting)
__device__ int g_midArr[PAIRS];   // mid tickets              (self-resetting)
__device__ int g_y1rdy[PAIRS];    // mids done per pair       (self-resetting)
__device__ int g_addArr[PAIRS];   // add tickets              (self-resetting)

// ---------------------------------------------------------------------------
// Half-plane reduce: one 256-thread CTA sums 8192 floats (8 float4/thread).
// Default-policy reads keep the batch L2-resident for its add (same segment).
// ---------------------------------------------------------------------------
__device__ __forceinline__ void half_reduce(const float* __restrict__ x,
                                            int plane, int half, int tid) {
    const float4* __restrict__ p =
        reinterpret_cast<const float4*>(x + (size_t)plane * HW) + half * HV;
    float s = 0.0f;
#pragma unroll
    for (int i = 0; i < HV / 256; ++i) {
        float4 v = p[tid + i * 256];
        s += (v.x + v.y) + (v.z + v.w);
    }
#pragma unroll
    for (int o = 16; o > 0; o >>= 1)
        s += __shfl_xor_sync(0xffffffffu, s, o);

    __shared__ float ws[8];
    if ((tid & 31) == 0) ws[tid >> 5] = s;
    __syncthreads();
    if (tid < 8) {
        float t = ws[tid];
#pragma unroll
        for (int o = 4; o > 0; o >>= 1)
            t += __shfl_xor_sync(0x000000ffu, t, o);
        if (tid == 0) g_part[plane * 2 + half] = t;
    }
}

// ---------------------------------------------------------------------------
// Half-plane add with inline bias (warp 0 dot + BN + relu6), then stream.
// Evict-first reads (dead after) and stores (protect resident reduce data).
// ---------------------------------------------------------------------------
__device__ __forceinline__ void half_add(
    const float* __restrict__ x, float* __restrict__ out,
    const float* __restrict__ w_fuse,
    const float* __restrict__ bn_gamma, const float* __restrict__ bn_beta,
    const float* __restrict__ bn_mean,  const float* __restrict__ bn_var,
    int b, int c, int half, int tid) {
    __shared__ float bsh;
    const int lane = tid & 31;

    if (tid < 32) {
        const float4* __restrict__ row =
            reinterpret_cast<const float4*>(w_fuse + (size_t)c * RR);
        const float4* __restrict__ y14 =
            reinterpret_cast<const float4*>(g_y1 + b * RR);
        float4 w = row[lane];
        float4 y = y14[lane];
        float acc = w.x * y.x;
        acc = fmaf(w.y, y.y, acc);
        acc = fmaf(w.z, y.z, acc);
        acc = fmaf(w.w, y.w, acc);
#pragma unroll
        for (int o = 16; o > 0; o >>= 1)
            acc += __shfl_xor_sync(0xffffffffu, acc, o);
        if (lane == 0) {
            const float inv_std = rsqrtf(bn_var[c] + 1e-5f);
            float v = fmaf((acc - bn_mean[c]) * inv_std, bn_gamma[c], bn_beta[c]);
            bsh = fminf(fmaxf(v, 0.0f), 6.0f);
        }
    }
    __syncthreads();
    const float bias = bsh;

    const int plane = b * CC + c;
    const float4* __restrict__ p =
        reinterpret_cast<const float4*>(x + (size_t)plane * HW) + half * HV;
    float4* __restrict__ o =
        reinterpret_cast<float4*>(out + (size_t)plane * HW) + half * HV;
#pragma unroll
    for (int i = 0; i < HV / 256; ++i) {
        float4 v = __ldcs(&p[tid + i * 256]);
        v.x += bias; v.y += bias; v.z += bias; v.w += bias;
        __stcs(&o[tid + i * 256], v);
    }
}

// ---------------------------------------------------------------------------
// Mid body: y1[b][r] = relu6((w_guide[r,:] @ sums[b]) / HW), one warp per r.
// sums[b][c] = g_part[(b*CC+c)*2] + g_part[(b*CC+c)*2+1].
// ---------------------------------------------------------------------------
__device__ __forceinline__ void mid_body(const float* __restrict__ w_guide,
                                         int b, int r, int lane) {
    const float4* __restrict__ row =
        reinterpret_cast<const float4*>(w_guide + (size_t)r * CC);
    const float4* __restrict__ pp =
        reinterpret_cast<const float4*>(g_part + (size_t)b * CC * 2);

    float acc = 0.0f;
#pragma unroll
    for (int j = 0; j < 4; ++j) {
        float4 w  = row[lane + 32 * j];
        float4 a0 = pp[2 * (lane + 32 * j)];
        float4 a1 = pp[2 * (lane + 32 * j) + 1];
        acc = fmaf(w.x, a0.x + a0.y, acc);
        acc = fmaf(w.y, a0.z + a0.w, acc);
        acc = fmaf(w.z, a1.x + a1.y, acc);
        acc = fmaf(w.w, a1.z + a1.w, acc);
    }
#pragma unroll
    for (int o = 16; o > 0; o >>= 1)
        acc += __shfl_xor_sync(0xffffffffu, acc, o);
    if (lane == 0) {
        float v = acc * (1.0f / (float)HW);
        g_y1[b * RR + r] = fminf(fmaxf(v, 0.0f), 6.0f);
    }
}

// ---------------------------------------------------------------------------
// Mega kernel: 4 pair-segments of [red | mid | add] in increasing bid order.
// Producers always have lower bids than their consumers, and the producer
// chain's roots (reds) never wait -> forward progress is guaranteed under
// in-order CTA dispatch. Counters self-reset via last-consumer tickets so
// every graph replay starts from the same state.
// ---------------------------------------------------------------------------
__global__ __launch_bounds__(256) void mega_kernel(
    const float* __restrict__ x, float* __restrict__ out,
    const float* __restrict__ w_guide,
    const float* __restrict__ w_fuse,
    const float* __restrict__ bn_gamma, const float* __restrict__ bn_beta,
    const float* __restrict__ bn_mean,  const float* __restrict__ bn_var) {
    const int bid = blockIdx.x;
    const int tid = threadIdx.x;
    const int g   = bid / SEG;
    const int r   = bid - g * SEG;

    if (r < REDN) {
        // -------- RED: half-plane reduce, then signal --------
        const int b   = 2 * g + (r >> 10);
        const int rem = r & 1023;
        half_reduce(x, b * CC + (rem >> 1), rem & 1, tid);
        if (tid == 0) {
            __threadfence();
            atomicAdd(&g_redCnt[g], 1);
        }
    } else if (r < REDN + MIDN) {
        // -------- MID: wait for all reds of this pair, compute y1 --------
        const int m = r - REDN;
        if (tid == 0) {
            while (*(volatile int*)&g_redCnt[g] < REDN) __nanosleep(64);
        }
        __syncthreads();
        mid_body(w_guide, 2 * g + (m >> 4), (m & 15) * 8 + (tid >> 5),
                 tid & 31);
        __syncthreads();
        if (tid == 0) {
            __threadfence();
            const int t = atomicAdd(&g_midArr[g], 1);
            atomicAdd(&g_y1rdy[g], 1);
            if (t == MIDN - 1) {            // last mid: reset red machinery
                g_redCnt[g] = 0;
                g_midArr[g] = 0;
            }
        }
    } else {
        // -------- ADD: wait for y1 of this pair, stream out = x + bias ----
        const int a = r - REDN - MIDN;
        if (tid == 0) {
            while (*(volatile int*)&g_y1rdy[g] < MIDN) __nanosleep(64);
            const int u = atomicAdd(&g_addArr[g], 1);
            if (u == ADDN - 1) {            // last add: reset y1 machinery
                g_y1rdy[g]  = 0;
                g_addArr[g] = 0;
            }
        }
        __syncthreads();
        const int b   = 2 * g + (a >> 10);
        const int rem = a & 1023;
        half_add(x, out, w_fuse, bn_gamma, bn_beta, bn_mean, bn_var,
                 b, rem >> 1, rem & 1, tid);
    }
}

extern "C" void kernel_launch(void* const* d_in, const int* in_sizes, int n_in,
                              void* d_out, int out_size) {
    const float* x        = (const float*)d_in[0];
    const float* w_guide  = (const float*)d_in[1];
    const float* w_fuse   = (const float*)d_in[2];
    const float* bn_gamma = (const float*)d_in[3];
    const float* bn_beta  = (const float*)d_in[4];
    const float* bn_mean  = (const float*)d_in[5];
    const float* bn_var   = (const float*)d_in[6];
    float* out = (float*)d_out;

    mega_kernel<<<PAIRS * SEG, 256>>>(x, out, w_guide, w_fuse,
                                      bn_gamma, bn_beta, bn_mean, bn_var);
}

// round 13
// speedup vs baseline: 1.2159x; 1.0219x over previous
#include <cuda_runtime.h>

// Problem constants (fixed by the reference setup_inputs)
#define BB 8
#define CC 512
#define RR 128
#define HW (128 * 128)
#define NPLANE (BB * CC)
#define HV (HW / 4 / 2)           // float4 elements per HALF plane (2048)

#define REDN 1024                 // red CTAs per batch (512 planes x 2 halves)
#define MIDN 16                   // mid CTAs per batch (16 x 8 warps = 128 rows)
#define ADDN 1024                 // add CTAs per batch
#define BLK  (2 * REDN + MIDN)    // middle block: interleaved add+red, then mid
#define GRID (REDN + MIDN + 7 * BLK + ADDN)   // 16512

// Scratch (no allocations allowed in kernel_launch)
__device__ __align__(16) float g_part[NPLANE * 2];  // half-plane partial sums
__device__ __align__(16) float g_y1[BB * RR];       // relu6(w_guide @ mean)
__device__ int g_redCnt[BB];      // reds done per batch   (self-resetting)
__device__ int g_midArr[BB];      // mid tickets           (self-resetting)
__device__ int g_y1rdy[BB];       // mids done per batch   (self-resetting)
__device__ int g_addArr[BB];      // add tickets           (self-resetting)

// ---------------------------------------------------------------------------
// Half-plane reduce: one 256-thread CTA sums 8192 floats (8 float4/thread).
// Default-policy reads keep the batch L2-resident for its upcoming add.
// ---------------------------------------------------------------------------
__device__ __forceinline__ void half_reduce(const float* __restrict__ x,
                                            int plane, int half, int tid) {
    const float4* __restrict__ p =
        reinterpret_cast<const float4*>(x + (size_t)plane * HW) + half * HV;
    float s = 0.0f;
#pragma unroll
    for (int i = 0; i < HV / 256; ++i) {
        float4 v = p[tid + i * 256];
        s += (v.x + v.y) + (v.z + v.w);
    }
#pragma unroll
    for (int o = 16; o > 0; o >>= 1)
        s += __shfl_xor_sync(0xffffffffu, s, o);

    __shared__ float ws[8];
    if ((tid & 31) == 0) ws[tid >> 5] = s;
    __syncthreads();
    if (tid < 8) {
        float t = ws[tid];
#pragma unroll
        for (int o = 4; o > 0; o >>= 1)
            t += __shfl_xor_sync(0x000000ffu, t, o);
        if (tid == 0) g_part[plane * 2 + half] = t;
    }
}

// ---------------------------------------------------------------------------
// Half-plane add with inline bias (warp 0 dot + BN + relu6), then stream.
// Evict-first reads (dead after; frees L2 for the incoming batch) and stores.
// ---------------------------------------------------------------------------
__device__ __forceinline__ void half_add(
    const float* __restrict__ x, float* __restrict__ out,
    const float* __restrict__ w_fuse,
    const float* __restrict__ bn_gamma, const float* __restrict__ bn_beta,
    const float* __restrict__ bn_mean,  const float* __restrict__ bn_var,
    int b, int c, int half, int tid) {
    __shared__ float bsh;
    const int lane = tid & 31;

    if (tid < 32) {
        const float4* __restrict__ row =
            reinterpret_cast<const float4*>(w_fuse + (size_t)c * RR);
        const float4* __restrict__ y14 =
            reinterpret_cast<const float4*>(g_y1 + b * RR);
        float4 w = row[lane];
        float4 y = y14[lane];
        float acc = w.x * y.x;
        acc = fmaf(w.y, y.y, acc);
        acc = fmaf(w.z, y.z, acc);
        acc = fmaf(w.w, y.w, acc);
#pragma unroll
        for (int o = 16; o > 0; o >>= 1)
            acc += __shfl_xor_sync(0xffffffffu, acc, o);
        if (lane == 0) {
            const float inv_std = rsqrtf(bn_var[c] + 1e-5f);
            float v = fmaf((acc - bn_mean[c]) * inv_std, bn_gamma[c], bn_beta[c]);
            bsh = fminf(fmaxf(v, 0.0f), 6.0f);
        }
    }
    __syncthreads();
    const float bias = bsh;

    const int plane = b * CC + c;
    const float4* __restrict__ p =
        reinterpret_cast<const float4*>(x + (size_t)plane * HW) + half * HV;
    float4* __restrict__ o =
        reinterpret_cast<float4*>(out + (size_t)plane * HW) + half * HV;
#pragma unroll
    for (int i = 0; i < HV / 256; ++i) {
        float4 v = __ldcs(&p[tid + i * 256]);
        v.x += bias; v.y += bias; v.z += bias; v.w += bias;
        __stcs(&o[tid + i * 256], v);
    }
}

// ---------------------------------------------------------------------------
// Mid body: y1[b][r] = relu6((w_guide[r,:] @ sums[b]) / HW), one warp per r.
// ---------------------------------------------------------------------------
__device__ __forceinline__ void mid_body(const float* __restrict__ w_guide,
                                         int b, int r, int lane) {
    const float4* __restrict__ row =
        reinterpret_cast<const float4*>(w_guide + (size_t)r * CC);
    const float4* __restrict__ pp =
        reinterpret_cast<const float4*>(g_part + (size_t)b * CC * 2);

    float acc = 0.0f;
#pragma unroll
    for (int j = 0; j < 4; ++j) {
        float4 w  = row[lane + 32 * j];
        float4 a0 = pp[2 * (lane + 32 * j)];
        float4 a1 = pp[2 * (lane + 32 * j) + 1];
        acc = fmaf(w.x, a0.x + a0.y, acc);
        acc = fmaf(w.y, a0.z + a0.w, acc);
        acc = fmaf(w.z, a1.x + a1.y, acc);
        acc = fmaf(w.w, a1.z + a1.w, acc);
    }
#pragma unroll
    for (int o = 16; o > 0; o >>= 1)
        acc += __shfl_xor_sync(0xffffffffu, acc, o);
    if (lane == 0) {
        float v = acc * (1.0f / (float)HW);
        g_y1[b * RR + r] = fminf(fmaxf(v, 0.0f), 6.0f);
    }
}

// ---------------------------------------------------------------------------
// Role helpers with signalling (self-resetting counters for graph replay).
// ---------------------------------------------------------------------------
__device__ __forceinline__ void do_red(const float* __restrict__ x,
                                       int b, int i, int tid) {
    half_reduce(x, b * CC + (i >> 1), i & 1, tid);
    if (tid == 0) {
        __threadfence();
        atomicAdd(&g_redCnt[b], 1);
    }
}

__device__ __forceinline__ void do_mid(const float* __restrict__ w_guide,
                                       int b, int m, int tid) {
    if (tid == 0)
        while (*(volatile int*)&g_redCnt[b] < REDN) __nanosleep(64);
    __syncthreads();
    mid_body(w_guide, b, m * 8 + (tid >> 5), tid & 31);
    __syncthreads();
    if (tid == 0) {
        __threadfence();
        const int t = atomicAdd(&g_midArr[b], 1);
        atomicAdd(&g_y1rdy[b], 1);
        if (t == MIDN - 1) {            // last mid: reset red machinery
            g_redCnt[b] = 0;
            g_midArr[b] = 0;
        }
    }
}

__device__ __forceinline__ void do_add(
    const float* __restrict__ x, float* __restrict__ out,
    const float* __restrict__ w_fuse,
    const float* __restrict__ bn_gamma, const float* __restrict__ bn_beta,
    const float* __restrict__ bn_mean,  const float* __restrict__ bn_var,
    int b, int i, int tid) {
    if (tid == 0) {
        while (*(volatile int*)&g_y1rdy[b] < MIDN) __nanosleep(64);
        const int u = atomicAdd(&g_addArr[b], 1);
        if (u == ADDN - 1) {            // last add: reset y1 machinery
            g_y1rdy[b]  = 0;
            g_addArr[b] = 0;
        }
    }
    __syncthreads();
    half_add(x, out, w_fuse, bn_gamma, bn_beta, bn_mean, bn_var,
             b, i >> 1, i & 1, tid);
}

// ---------------------------------------------------------------------------
// Mega kernel with interleaved segments:
//   [red(0):1024][mid(0):16]
//   b=0..6: [ even->add(b), odd->red(b+1) : 2048 ][ mid(b+1):16 ]
//   [add(7):1024]
// Spinning add CTAs are interleaved with never-waiting red CTAs, so SMs stay
// busy through every dependency boundary. Producers always precede consumers
// in bid order and root producers never wait -> no deadlock.
// ---------------------------------------------------------------------------
__global__ __launch_bounds__(256) void mega_kernel(
    const float* __restrict__ x, float* __restrict__ out,
    const float* __restrict__ w_guide,
    const float* __restrict__ w_fuse,
    const float* __restrict__ bn_gamma, const float* __restrict__ bn_beta,
    const float* __restrict__ bn_mean,  const float* __restrict__ bn_var) {
    const int bid = blockIdx.x;
    const int tid = threadIdx.x;

    if (bid < REDN) {
        do_red(x, 0, bid, tid);
    } else if (bid < REDN + MIDN) {
        do_mid(w_guide, 0, bid - REDN, tid);
    } else if (bid < REDN + MIDN + 7 * BLK) {
        const int t   = bid - (REDN + MIDN);
        const int b   = t / BLK;
        const int off = t - b * BLK;
        if (off < 2 * REDN) {
            if (off & 1)
                do_red(x, b + 1, off >> 1, tid);
            else
                do_add(x, out, w_fuse, bn_gamma, bn_beta, bn_mean, bn_var,
                       b, off >> 1, tid);
        } else {
            do_mid(w_guide, b + 1, off - 2 * REDN, tid);
        }
    } else {
        do_add(x, out, w_fuse, bn_gamma, bn_beta, bn_mean, bn_var,
               BB - 1, bid - (REDN + MIDN + 7 * BLK), tid);
    }
}

extern "C" void kernel_launch(void* const* d_in, const int* in_sizes, int n_in,
                              void* d_out, int out_size) {
    const float* x        = (const float*)d_in[0];
    const float* w_guide  = (const float*)d_in[1];
    const float* w_fuse   = (const float*)d_in[2];
    const float* bn_gamma = (const float*)d_in[3];
    const float* bn_beta  = (const float*)d_in[4];
    const float* bn_mean  = (const float*)d_in[5];
    const float* bn_var   = (const float*)d_in[6];
    float* out = (float*)d_out;

    mega_kernel<<<GRID, 256>>>(x, out, w_guide, w_fuse,
                               bn_gamma, bn_beta, bn_mean, bn_var);
}